// round 13
// baseline (speedup 1.0000x reference)
#include <cuda_runtime.h>
#include <cuda_bf16.h>

// M=64, G=48, N=4096, GRID_RANGE=2.0
// Inputs: 0:x(N) 1:y(N) 2:z(N) 3:mu_x(M*G) 4:mu_y(M*G) 5:mu_z(M*G)
//         6:sigmas(M*G*3) 7:r(M*G*4) 8:weight(M*G)
// Output: float (N, M) row-major.

#define MDIM 64
#define GDIM 48
#define NWARP 8           // warps per block
#define WSLICE 144        // float4 slots per warp slice (generic: 48*3)

__device__ __forceinline__ float fast_exp2(float q) {
    float p; asm("ex2.approx.ftz.f32 %0, %1;" : "=f"(p) : "f"(q)); return p;
}

// Single fused kernel. One m per block (blockIdx.y); 512 points per block,
// 2 per thread; grid (8, 64) = 512 blocks.
//
// BARRIER-FREE PROLOGUE: each warp builds its own private copy of the 48
// coefficient sets into its own smem slice. Lane l handles g = l and
// g = l + 32 (l < 16). Only __syncwarp() orders build vs loop — no
// __syncthreads, no inter-warp coupling, no divergent t<48 tail.
//
// Iso fast path (A = a*I, a common to all g):
//   out = exp2(a*|p|^2) * sum_g (w_g*exp2(c_g)) * exp2(b_g.p)
// Hot loop per (g,point): 0.5 LDS.128 {b0,b1,b2,w'}, 3 FMA, 1 MUFU, 1 acc FMA.
__global__ __launch_bounds__(256) void gauss_fused_kernel(
    const float* __restrict__ xs, const float* __restrict__ ys,
    const float* __restrict__ zs,
    const float* __restrict__ mu_x, const float* __restrict__ mu_y,
    const float* __restrict__ mu_z, const float* __restrict__ sigmas,
    const float* __restrict__ rq, const float* __restrict__ weight,
    float* __restrict__ out, int N) {
    __shared__ __align__(16) float4 sc[NWARP * WSLICE];   // 18 KB

    const int m    = blockIdx.y;
    const int t    = threadIdx.x;
    const int wid  = t >> 5;
    const int lane = t & 31;
    const int n0 = blockIdx.x * 512 + t;
    const int n1 = n0 + 256;

    // ---- point loads first (independent of everything) ----
    float x0 = 0.f, y0 = 0.f, z0 = 0.f;
    float x1 = 0.f, y1 = 0.f, z1 = 0.f;
    if (n0 < N) { x0 = xs[n0]; y0 = ys[n0] + 1.f; z0 = zs[n0] + 1.f; }
    if (n1 < N) { x1 = xs[n1]; y1 = ys[n1] + 1.f; z1 = zs[n1] + 1.f; }

    // ---- per-warp coefficient build: lane -> g=lane, g=lane+32 (lane<16) ----
    const bool two = (lane < 16);
    const int idx0 = m * GDIM + lane;
    const int idx1 = m * GDIM + 32 + (lane & 15);   // dup read for lane>=16

    const float4 qa = reinterpret_cast<const float4*>(rq)[idx0];
    const float4 qb = reinterpret_cast<const float4*>(rq)[idx1];
    const float sa0 = sigmas[idx0 * 3 + 0];
    const float sa1 = sigmas[idx0 * 3 + 1];
    const float sa2 = sigmas[idx0 * 3 + 2];
    const float sb0 = sigmas[idx1 * 3 + 0];
    const float sb1 = sigmas[idx1 * 3 + 1];
    const float sb2 = sigmas[idx1 * 3 + 2];
    const float sg0 = sigmas[(m * GDIM) * 3];       // uniform broadcast
    const float ma0 = mu_x[idx0], ma1 = mu_y[idx0], ma2 = mu_z[idx0];
    const float mb0 = mu_x[idx1], mb1 = mu_y[idx1], mb2 = mu_z[idx1];
    const float wa = weight[idx0], wb = weight[idx1];

    const int predA = (qa.y == 0.f) & (qa.z == 0.f) & (qa.w == 0.f) &
                      (sa0 == sa1) & (sa0 == sa2) & (sa0 == sg0);
    const int predB = (qb.y == 0.f) & (qb.z == 0.f) & (qb.w == 0.f) &
                      (sb0 == sb1) & (sb0 == sb2) & (sb0 == sg0);
    const int iso = __all_sync(0xffffffffu, predA & (two ? predB : 1));

    const float kk = -0.72134752044448169f;  // -0.5 * log2(e)
    float4* __restrict__ ws = sc + wid * WSLICE;
    float a = 0.f;

    if (iso) {
        a = kk * __fdividef(1.f, sa0 * sa0);     // uniform across lanes
        {
            const float b0 = -2.f * (a * ma0);
            const float b1 = -2.f * (a * ma1);
            const float b2 = -2.f * (a * ma2);
            const float c = a * (ma0 * ma0 + ma1 * ma1 + ma2 * ma2);
            ws[lane] = make_float4(b0, b1, b2, wa * fast_exp2(c));
        }
        if (two) {
            const float b0 = -2.f * (a * mb0);
            const float b1 = -2.f * (a * mb1);
            const float b2 = -2.f * (a * mb2);
            const float c = a * (mb0 * mb0 + mb1 * mb1 + mb2 * mb2);
            ws[32 + lane] = make_float4(b0, b1, b2, wb * fast_exp2(c));
        }
    } else {
        // cold generic build: lane builds full coeffs for its g's
        #pragma unroll
        for (int pass = 0; pass < 2; ++pass) {
            if (pass == 1 && !two) break;
            const float4 q4 = pass ? qb : qa;
            const float t0 = pass ? sb0 : sa0;
            const float t1 = pass ? sb1 : sa1;
            const float t2 = pass ? sb2 : sa2;
            const float u0 = pass ? mb0 : ma0;
            const float u1 = pass ? mb1 : ma1;
            const float u2 = pass ? mb2 : ma2;
            const float w  = pass ? wb : wa;
            const int gg   = pass ? (32 + lane) : lane;

            const float inv = rsqrtf(q4.x * q4.x + q4.y * q4.y +
                                     q4.z * q4.z + q4.w * q4.w);
            const float nw = q4.x * inv, nx = q4.y * inv,
                        ny = q4.z * inv, nz = q4.w * inv;
            float R[3][3];
            R[0][0] = 1.f - 2.f * (ny * ny + nz * nz);
            R[0][1] = 2.f * (nx * ny - nw * nz);
            R[0][2] = 2.f * (nx * nz + nw * ny);
            R[1][0] = 2.f * (nx * ny + nw * nz);
            R[1][1] = 1.f - 2.f * (nx * nx + nz * nz);
            R[1][2] = 2.f * (ny * nz - nw * nx);
            R[2][0] = 2.f * (nx * nz - nw * ny);
            R[2][1] = 2.f * (ny * nz + nw * nx);
            R[2][2] = 1.f - 2.f * (nx * nx + ny * ny);
            const float is0 = 1.f / (t0 * t0);
            const float is1 = 1.f / (t1 * t1);
            const float is2 = 1.f / (t2 * t2);
            float A[3][3];
            #pragma unroll
            for (int i = 0; i < 3; ++i)
                #pragma unroll
                for (int j = 0; j < 3; ++j)
                    A[i][j] = kk * (R[i][0] * R[j][0] * is0 +
                                    R[i][1] * R[j][1] * is1 +
                                    R[i][2] * R[j][2] * is2);
            const float b0 = -2.f * (A[0][0] * u0 + A[0][1] * u1 + A[0][2] * u2);
            const float b1 = -2.f * (A[1][0] * u0 + A[1][1] * u1 + A[1][2] * u2);
            const float b2 = -2.f * (A[2][0] * u0 + A[2][1] * u1 + A[2][2] * u2);
            const float c  = A[0][0] * u0 * u0 + A[1][1] * u1 * u1 + A[2][2] * u2 * u2
                     + 2.f * (A[0][1] * u0 * u1 + A[0][2] * u0 * u2 + A[1][2] * u1 * u2);
            ws[gg * 3 + 0] = make_float4(A[0][0], A[1][1], A[2][2], 2.f * A[0][1]);
            ws[gg * 3 + 1] = make_float4(2.f * A[0][2], 2.f * A[1][2], b0, b1);
            ws[gg * 3 + 2] = make_float4(b2, c, w, 0.f);
        }
    }
    __syncwarp();

    float r0, r1;
    if (iso) {
        const float s20 = fmaf(z0, z0, fmaf(y0, y0, x0 * x0));
        const float s21 = fmaf(z1, z1, fmaf(y1, y1, x1 * x1));
        const float E0 = fast_exp2(a * s20);
        const float E1 = fast_exp2(a * s21);

        float acc00 = 0.f, acc01 = 0.f, acc10 = 0.f, acc11 = 0.f;
        const float4* __restrict__ p = ws;
        #pragma unroll
        for (int g = 0; g < GDIM; g += 2, p += 2) {
            const float4 B0 = p[0];
            const float4 B1 = p[1];
            const float qa0 = fmaf(B0.x, x0, fmaf(B0.y, y0, B0.z * z0));
            const float qb0 = fmaf(B1.x, x0, fmaf(B1.y, y0, B1.z * z0));
            const float qa1 = fmaf(B0.x, x1, fmaf(B0.y, y1, B0.z * z1));
            const float qb1 = fmaf(B1.x, x1, fmaf(B1.y, y1, B1.z * z1));
            acc00 = fmaf(B0.w, fast_exp2(qa0), acc00);
            acc01 = fmaf(B1.w, fast_exp2(qb0), acc01);
            acc10 = fmaf(B0.w, fast_exp2(qa1), acc10);
            acc11 = fmaf(B1.w, fast_exp2(qb1), acc11);
        }
        r0 = E0 * (acc00 + acc01);
        r1 = E1 * (acc10 + acc11);
    } else {
        const float xx0 = x0 * x0, yy0 = y0 * y0, zz0 = z0 * z0;
        const float xy0 = x0 * y0, xz0 = x0 * z0, yz0 = y0 * z0;
        const float xx1 = x1 * x1, yy1 = y1 * y1, zz1 = z1 * z1;
        const float xy1 = x1 * y1, xz1 = x1 * z1, yz1 = y1 * z1;
        float acc0 = 0.f, acc1 = 0.f;
        #pragma unroll 4
        for (int g = 0; g < GDIM; ++g) {
            const float4 cA = ws[g * 3 + 0];
            const float4 cB = ws[g * 3 + 1];
            const float4 cC = ws[g * 3 + 2];
            float qq0 = cC.y;
            qq0 = fmaf(cA.x, xx0, qq0);
            qq0 = fmaf(cA.y, yy0, qq0);
            qq0 = fmaf(cA.z, zz0, qq0);
            qq0 = fmaf(cA.w, xy0, qq0);
            qq0 = fmaf(cB.x, xz0, qq0);
            qq0 = fmaf(cB.y, yz0, qq0);
            qq0 = fmaf(cB.z, x0, qq0);
            qq0 = fmaf(cB.w, y0, qq0);
            qq0 = fmaf(cC.x, z0, qq0);
            float qq1 = cC.y;
            qq1 = fmaf(cA.x, xx1, qq1);
            qq1 = fmaf(cA.y, yy1, qq1);
            qq1 = fmaf(cA.z, zz1, qq1);
            qq1 = fmaf(cA.w, xy1, qq1);
            qq1 = fmaf(cB.x, xz1, qq1);
            qq1 = fmaf(cB.y, yz1, qq1);
            qq1 = fmaf(cB.z, x1, qq1);
            qq1 = fmaf(cB.w, y1, qq1);
            qq1 = fmaf(cC.x, z1, qq1);
            acc0 = fmaf(cC.z, fast_exp2(qq0), acc0);
            acc1 = fmaf(cC.z, fast_exp2(qq1), acc1);
        }
        r0 = acc0;
        r1 = acc1;
    }

    if (n0 < N) out[n0 * MDIM + m] = r0;
    if (n1 < N) out[n1 * MDIM + m] = r1;
}

extern "C" void kernel_launch(void* const* d_in, const int* in_sizes, int n_in,
                              void* d_out, int out_size) {
    const float* x      = (const float*)d_in[0];
    const float* y      = (const float*)d_in[1];
    const float* z      = (const float*)d_in[2];
    const float* mu_x   = (const float*)d_in[3];
    const float* mu_y   = (const float*)d_in[4];
    const float* mu_z   = (const float*)d_in[5];
    const float* sigmas = (const float*)d_in[6];
    const float* r      = (const float*)d_in[7];
    const float* weight = (const float*)d_in[8];
    float* out = (float*)d_out;

    const int N = in_sizes[0];

    dim3 grid((N + 511) / 512, MDIM);
    gauss_fused_kernel<<<grid, 256>>>(x, y, z, mu_x, mu_y, mu_z,
                                      sigmas, r, weight, out, N);
}